// round 1
// baseline (speedup 1.0000x reference)
#include <cuda_runtime.h>
#include <cuda_bf16.h>

#define IN_F   48
#define EDGE_F 32
#define CAT_F  96   // 2*IN_F
#define HID_F  128
#define OUT_F  64
#define N_MAX  100000
#define E_MAX  1600000

// ---------------- scratch (static device globals; no allocation) -------------
__device__ float g_deg [N_MAX];           // after k_invdeg: 1/max(deg,1)
__device__ float g_acc0[N_MAX * IN_F];    // sum of edge messages (layer 0)
__device__ float g_h   [N_MAX * CAT_F];   // concat(nfeat, mean0)
__device__ float g_acc1[N_MAX * CAT_F];   // sum h[src] per dst
__device__ float g_h1  [N_MAX * HID_F];   // layer-1 activations
__device__ float g_acc2[N_MAX * HID_F];   // sum h1[src] per dst

// ---------------- helpers ----------------------------------------------------
__device__ __forceinline__ void red_add4(float* a, float4 v) {
    asm volatile("red.global.add.v4.f32 [%0], {%1,%2,%3,%4};"
                 :: "l"(a), "f"(v.x), "f"(v.y), "f"(v.z), "f"(v.w) : "memory");
}
__device__ __forceinline__ void red_add1(float* a, float v) {
    asm volatile("red.global.add.f32 [%0], %1;" :: "l"(a), "f"(v) : "memory");
}

// ---------------- K1: degree -------------------------------------------------
__global__ void k_deg(const int* __restrict__ dst, int E) {
    int i = blockIdx.x * blockDim.x + threadIdx.x;
    if (i < E) red_add1(&g_deg[dst[i]], 1.0f);
}

__global__ void k_invdeg(int n) {
    int i = blockIdx.x * blockDim.x + threadIdx.x;
    if (i < n) g_deg[i] = 1.0f / fmaxf(g_deg[i], 1.0f);
}

// ---------------- K2: fused edge encoder + u_mul_e + scatter -----------------
// blockDim MUST be 256. Tiles of 16 edges. enc = relu(efeat @ We + be);
// m = nfeat[src] * enc; red-add to g_acc0[dst].
__global__ void k_msg1(const float* __restrict__ nfeat,
                       const float* __restrict__ efeat,
                       const int*   __restrict__ src,
                       const int*   __restrict__ dst,
                       const float* __restrict__ We,
                       const float* __restrict__ be, int E) {
    __shared__ float sWe[EDGE_F * IN_F];
    __shared__ float sbe[IN_F];
    __shared__ __align__(16) float sef [16][EDGE_F];
    __shared__ __align__(16) float senc[16][IN_F];
    __shared__ int ssrc[16], sdst[16];

    int tid = threadIdx.x;
    for (int i = tid; i < EDGE_F * IN_F; i += 256) sWe[i] = We[i];
    if (tid < IN_F) sbe[tid] = be[tid];
    __syncthreads();

    int ntiles = (E + 15) / 16;
    for (int t = blockIdx.x; t < ntiles; t += gridDim.x) {
        int e0 = t * 16;
        // stage edge features + indices
        for (int i = tid; i < 16 * EDGE_F; i += 256) {
            int ed = i >> 5, c = i & 31;
            int e = e0 + ed;
            sef[ed][c] = (e < E) ? efeat[e * EDGE_F + c] : 0.0f;
        }
        if (tid < 16) {
            int e = e0 + tid;
            if (e < E) { ssrc[tid] = src[e]; sdst[tid] = dst[e]; }
        }
        __syncthreads();
        // 16 edges * 48 outputs = 768 = 3*256 work items
        #pragma unroll
        for (int r = 0; r < 3; r++) {
            int idx = tid + r * 256;
            int ed = idx / IN_F, j = idx - ed * IN_F;
            float a = sbe[j];
            #pragma unroll
            for (int k = 0; k < EDGE_F; k++)
                a = fmaf(sef[ed][k], sWe[k * IN_F + j], a);
            senc[ed][j] = fmaxf(a, 0.0f);
        }
        __syncthreads();
        // scatter: 16 edges * 12 float4 chunks
        if (tid < 16 * 12) {
            int ed = tid / 12, c = tid - ed * 12;
            int e = e0 + ed;
            if (e < E) {
                int s = ssrc[ed], d = sdst[ed];
                float4 nf = *reinterpret_cast<const float4*>(nfeat + s * IN_F + c * 4);
                float4 en = *reinterpret_cast<const float4*>(&senc[ed][c * 4]);
                float4 m = make_float4(nf.x * en.x, nf.y * en.y, nf.z * en.z, nf.w * en.w);
                red_add4(&g_acc0[d * IN_F + c * 4], m);
            }
        }
        __syncthreads();
    }
}

// ---------------- K3: build h = [nfeat | acc0 * invdeg] ----------------------
__global__ void k_finh(const float* __restrict__ nfeat, int n) {
    int idx = blockIdx.x * blockDim.x + threadIdx.x;
    if (idx < n * IN_F) {
        int i = idx / IN_F, j = idx - i * IN_F;
        g_h[i * CAT_F + j]        = nfeat[idx];
        g_h[i * CAT_F + IN_F + j] = g_acc0[idx] * g_deg[i];
    }
}

// ---------------- K4/K6: generic gather+scatter (warp per edge) --------------
template <int F>
__global__ void k_scatter(const float* __restrict__ rows,
                          const int* __restrict__ src,
                          const int* __restrict__ dst,
                          float* __restrict__ acc, int E) {
    int w = (blockIdx.x * blockDim.x + threadIdx.x) >> 5;
    int lane = threadIdx.x & 31;
    if (w >= E) return;
    int s = src[w], d = dst[w];   // uniform per warp -> broadcast load
    constexpr int C = F / 4;
    if (lane < C) {
        float4 v = *reinterpret_cast<const float4*>(rows + s * F + lane * 4);
        red_add4(acc + d * F + lane * 4, v);
    }
}

// ---------------- K5: h1 = relu(h@W1s + mean1@W1n + b1) ----------------------
// block 128 threads (one per output channel), 16 nodes per block
__global__ void k_node1(const float* __restrict__ W1s,
                        const float* __restrict__ W1n,
                        const float* __restrict__ b1, int n) {
    __shared__ float hs[16][CAT_F];
    __shared__ float hn[16][CAT_F];
    int tid = threadIdx.x;
    int node0 = blockIdx.x * 16;
    for (int i = tid; i < 16 * CAT_F; i += 128) {
        int r = i / CAT_F, k = i - r * CAT_F;
        int nd = node0 + r;
        if (nd < n) {
            hs[r][k] = g_h[nd * CAT_F + k];
            hn[r][k] = g_acc1[nd * CAT_F + k] * g_deg[nd];
        }
    }
    __syncthreads();
    int j = tid;
    float acc[16];
    float bj = b1[j];
    #pragma unroll
    for (int i = 0; i < 16; i++) acc[i] = bj;
    for (int k = 0; k < CAT_F; k++) {
        float ws = W1s[k * HID_F + j];
        float wn = W1n[k * HID_F + j];
        #pragma unroll
        for (int i = 0; i < 16; i++)
            acc[i] = fmaf(hs[i][k], ws, fmaf(hn[i][k], wn, acc[i]));
    }
    #pragma unroll
    for (int i = 0; i < 16; i++) {
        int nd = node0 + i;
        if (nd < n) g_h1[nd * HID_F + j] = fmaxf(acc[i], 0.0f);
    }
}

// ---------------- K7: out = h1@W2s + mean2@W2n + b2 --------------------------
// block 64 threads (one per output channel), 16 nodes per block
__global__ void k_node2(const float* __restrict__ W2s,
                        const float* __restrict__ W2n,
                        const float* __restrict__ b2,
                        float* __restrict__ out, int n) {
    __shared__ float hs[16][HID_F];
    __shared__ float hn[16][HID_F];
    int tid = threadIdx.x;
    int node0 = blockIdx.x * 16;
    for (int i = tid; i < 16 * HID_F; i += 64) {
        int r = i >> 7, k = i & 127;
        int nd = node0 + r;
        if (nd < n) {
            hs[r][k] = g_h1[nd * HID_F + k];
            hn[r][k] = g_acc2[nd * HID_F + k] * g_deg[nd];
        }
    }
    __syncthreads();
    int j = tid;
    float acc[16];
    float bj = b2[j];
    #pragma unroll
    for (int i = 0; i < 16; i++) acc[i] = bj;
    for (int k = 0; k < HID_F; k++) {
        float ws = W2s[k * OUT_F + j];
        float wn = W2n[k * OUT_F + j];
        #pragma unroll
        for (int i = 0; i < 16; i++)
            acc[i] = fmaf(hs[i][k], ws, fmaf(hn[i][k], wn, acc[i]));
    }
    #pragma unroll
    for (int i = 0; i < 16; i++) {
        int nd = node0 + i;
        if (nd < n) out[nd * OUT_F + j] = acc[i];
    }
}

// ---------------- launch -----------------------------------------------------
extern "C" void kernel_launch(void* const* d_in, const int* in_sizes, int n_in,
                              void* d_out, int out_size) {
    const float* nfeat = (const float*)d_in[0];
    const float* efeat = (const float*)d_in[1];
    const int*   src   = (const int*)  d_in[2];
    const int*   dst   = (const int*)  d_in[3];
    const float* We    = (const float*)d_in[4];
    const float* be    = (const float*)d_in[5];
    const float* W1s   = (const float*)d_in[6];
    const float* W1n   = (const float*)d_in[7];
    const float* b1    = (const float*)d_in[8];
    const float* W2s   = (const float*)d_in[9];
    const float* W2n   = (const float*)d_in[10];
    const float* b2    = (const float*)d_in[11];
    float* out = (float*)d_out;

    int n = in_sizes[0] / IN_F;
    int E = in_sizes[2];

    void *p_deg, *p_acc0, *p_h, *p_acc1, *p_h1, *p_acc2;
    cudaGetSymbolAddress(&p_deg,  g_deg);
    cudaGetSymbolAddress(&p_acc0, g_acc0);
    cudaGetSymbolAddress(&p_h,    g_h);
    cudaGetSymbolAddress(&p_acc1, g_acc1);
    cudaGetSymbolAddress(&p_h1,   g_h1);
    cudaGetSymbolAddress(&p_acc2, g_acc2);

    cudaMemsetAsync(p_deg,  0, (size_t)n * sizeof(float), 0);
    cudaMemsetAsync(p_acc0, 0, (size_t)n * IN_F  * sizeof(float), 0);
    cudaMemsetAsync(p_acc1, 0, (size_t)n * CAT_F * sizeof(float), 0);
    cudaMemsetAsync(p_acc2, 0, (size_t)n * HID_F * sizeof(float), 0);

    k_deg<<<(E + 255) / 256, 256>>>(dst, E);
    k_invdeg<<<(n + 255) / 256, 256>>>(n);

    k_msg1<<<2048, 256>>>(nfeat, efeat, src, dst, We, be, E);
    k_finh<<<(n * IN_F + 255) / 256, 256>>>(nfeat, n);

    // layer 1 neighbor mean: sum h[src] into acc1
    k_scatter<CAT_F><<<(E + 7) / 8, 256>>>((const float*)p_h, src, dst, (float*)p_acc1, E);
    k_node1<<<(n + 15) / 16, 128>>>(W1s, W1n, b1, n);

    // layer 2 neighbor mean: sum h1[src] into acc2
    k_scatter<HID_F><<<(E + 7) / 8, 256>>>((const float*)p_h1, src, dst, (float*)p_acc2, E);
    k_node2<<<(n + 15) / 16, 64>>>(W2s, W2n, b2, out, n);
}

// round 3
// speedup vs baseline: 1.3058x; 1.3058x over previous
#include <cuda_runtime.h>
#include <cuda_bf16.h>

#define IN_F   48
#define EDGE_F 32
#define CAT_F  96   // 2*IN_F
#define HID_F  128
#define OUT_F  64
#define N_MAX  100032
#define E_MAX  1600000

// ---------------- scratch (static device globals; no allocation) -------------
__device__ int   g_degi  [N_MAX];         // in-degree (int)
__device__ int   g_off   [N_MAX + 1];     // CSR row offsets (by dst)
__device__ int   g_cursor[N_MAX];         // fill cursors
__device__ int   g_bsum  [128];           // block sums for scan
__device__ int   g_esrc  [E_MAX];         // src node id per CSR slot
__device__ float g_acc0  [N_MAX * IN_F];  // sum of edge messages (layer 0)
__device__ float g_h     [N_MAX * CAT_F]; // concat(nfeat, mean0)
__device__ float g_hn1   [N_MAX * CAT_F]; // mean of h[src] per dst
__device__ float g_h1    [N_MAX * HID_F]; // layer-1 activations
__device__ float g_z2    [N_MAX * OUT_F]; // h1 @ W2n

// ---------------- helpers ----------------------------------------------------
__device__ __forceinline__ void red_add4(float* a, float4 v) {
    asm volatile("red.global.add.v4.f32 [%0], {%1,%2,%3,%4};"
                 :: "l"(a), "f"(v.x), "f"(v.y), "f"(v.z), "f"(v.w) : "memory");
}
__device__ __forceinline__ float4 f4add(float4 a, float4 b) {
    return make_float4(a.x + b.x, a.y + b.y, a.z + b.z, a.w + b.w);
}

// ---------------- CSR build --------------------------------------------------
__global__ void k_degi(const int* __restrict__ dst, int E) {
    int i = blockIdx.x * blockDim.x + threadIdx.x;
    if (i < E) atomicAdd(&g_degi[dst[i]], 1);
}

__global__ void k_scan1(int n) {
    __shared__ int sh[1024];
    int t = threadIdx.x, i = blockIdx.x * 1024 + t;
    int v = (i < n) ? g_degi[i] : 0;
    sh[t] = v; __syncthreads();
    for (int off = 1; off < 1024; off <<= 1) {
        int x = (t >= off) ? sh[t - off] : 0;
        __syncthreads();
        sh[t] += x;
        __syncthreads();
    }
    if (i < n) g_off[i] = sh[t] - v;       // exclusive within block
    if (t == 1023) g_bsum[blockIdx.x] = sh[1023];
}

__global__ void k_scan2(int nb) {
    __shared__ int sh[128];
    int t = threadIdx.x;
    sh[t] = (t < nb) ? g_bsum[t] : 0;
    __syncthreads();
    if (t == 0) {
        int run = 0;
        for (int j = 0; j < nb; j++) { int x = sh[j]; sh[j] = run; run += x; }
    }
    __syncthreads();
    if (t < nb) g_bsum[t] = sh[t];
}

__global__ void k_scan3(int n, int E) {
    int i = blockIdx.x * blockDim.x + threadIdx.x;
    if (i < n) {
        int v = g_off[i] + g_bsum[i >> 10];
        g_off[i] = v;
        g_cursor[i] = v;
    }
    if (i == 0) g_off[n] = E;
}

__global__ void k_fill(const int* __restrict__ src, const int* __restrict__ dst, int E) {
    int i = blockIdx.x * blockDim.x + threadIdx.x;
    if (i < E) {
        int p = atomicAdd(&g_cursor[dst[i]], 1);
        g_esrc[p] = src[i];
    }
}

// ---------------- K2: fused edge encoder + u_mul_e + scatter -----------------
__global__ void k_msg1(const float* __restrict__ nfeat,
                       const float* __restrict__ efeat,
                       const int*   __restrict__ src,
                       const int*   __restrict__ dst,
                       const float* __restrict__ We,
                       const float* __restrict__ be, int E) {
    __shared__ float sWe[EDGE_F * IN_F];
    __shared__ float sbe[IN_F];
    __shared__ __align__(16) float sef [16][EDGE_F];
    __shared__ __align__(16) float senc[16][IN_F];
    __shared__ int ssrc[16], sdst[16];

    int tid = threadIdx.x;
    for (int i = tid; i < EDGE_F * IN_F; i += 256) sWe[i] = We[i];
    if (tid < IN_F) sbe[tid] = be[tid];
    __syncthreads();

    int ntiles = (E + 15) / 16;
    for (int t = blockIdx.x; t < ntiles; t += gridDim.x) {
        int e0 = t * 16;
        for (int i = tid; i < 16 * EDGE_F; i += 256) {
            int ed = i >> 5, c = i & 31;
            int e = e0 + ed;
            sef[ed][c] = (e < E) ? efeat[e * EDGE_F + c] : 0.0f;
        }
        if (tid < 16) {
            int e = e0 + tid;
            if (e < E) { ssrc[tid] = src[e]; sdst[tid] = dst[e]; }
        }
        __syncthreads();
        #pragma unroll
        for (int r = 0; r < 3; r++) {
            int idx = tid + r * 256;
            int ed = idx / IN_F, j = idx - ed * IN_F;
            float a = sbe[j];
            #pragma unroll
            for (int k = 0; k < EDGE_F; k++)
                a = fmaf(sef[ed][k], sWe[k * IN_F + j], a);
            senc[ed][j] = fmaxf(a, 0.0f);
        }
        __syncthreads();
        if (tid < 16 * 12) {
            int ed = tid / 12, c = tid - ed * 12;
            int e = e0 + ed;
            if (e < E) {
                int s = ssrc[ed], d = sdst[ed];
                float4 nf = *reinterpret_cast<const float4*>(nfeat + s * IN_F + c * 4);
                float4 en = *reinterpret_cast<const float4*>(&senc[ed][c * 4]);
                float4 m = make_float4(nf.x * en.x, nf.y * en.y, nf.z * en.z, nf.w * en.w);
                red_add4(&g_acc0[d * IN_F + c * 4], m);
            }
        }
        __syncthreads();
    }
}

// ---------------- K3: build h = [nfeat | acc0 * invdeg] ----------------------
__global__ void k_finh(const float* __restrict__ nfeat, int n) {
    int idx = blockIdx.x * blockDim.x + threadIdx.x;
    if (idx < n * IN_F) {
        int i = idx / IN_F, j = idx - i * IN_F;
        int d = g_off[i + 1] - g_off[i];
        float inv = (d > 0) ? 1.0f / (float)d : 0.0f;
        g_h[i * CAT_F + j]        = nfeat[idx];
        g_h[i * CAT_F + IN_F + j] = g_acc0[idx] * inv;
    }
}

// ---------------- gather-mean, F=96 (warp per node, 24 active lanes) ---------
__global__ void k_gather96(const float* __restrict__ rows,
                           float* __restrict__ outm, int n) {
    int w = (blockIdx.x * blockDim.x + threadIdx.x) >> 5;
    if (w >= n) return;
    int lane = threadIdx.x & 31;
    int beg = g_off[w], end = g_off[w + 1];
    int col = lane * 4;
    bool act = lane < 24;
    float4 acc = make_float4(0.f, 0.f, 0.f, 0.f);
    int e = beg;
    for (; e + 4 <= end; e += 4) {
        int s0 = g_esrc[e], s1 = g_esrc[e + 1], s2 = g_esrc[e + 2], s3 = g_esrc[e + 3];
        if (act) {
            float4 v0 = *reinterpret_cast<const float4*>(rows + (size_t)s0 * CAT_F + col);
            float4 v1 = *reinterpret_cast<const float4*>(rows + (size_t)s1 * CAT_F + col);
            float4 v2 = *reinterpret_cast<const float4*>(rows + (size_t)s2 * CAT_F + col);
            float4 v3 = *reinterpret_cast<const float4*>(rows + (size_t)s3 * CAT_F + col);
            acc = f4add(acc, f4add(f4add(v0, v1), f4add(v2, v3)));
        }
    }
    for (; e < end; e++) {
        int s = g_esrc[e];
        if (act) {
            float4 v = *reinterpret_cast<const float4*>(rows + (size_t)s * CAT_F + col);
            acc = f4add(acc, v);
        }
    }
    if (act) {
        float inv = (end > beg) ? 1.0f / (float)(end - beg) : 0.0f;
        *reinterpret_cast<float4*>(outm + (size_t)w * CAT_F + col) =
            make_float4(acc.x * inv, acc.y * inv, acc.z * inv, acc.w * inv);
    }
}

// ---------------- gather-mean-add, F=64 (2 nodes per warp) -------------------
__global__ void k_gather64_add(const float* __restrict__ rows,
                               float* __restrict__ out, int n) {
    int w = (blockIdx.x * blockDim.x + threadIdx.x) >> 5;
    int lane = threadIdx.x & 31;
    int half = lane >> 4;
    int l16  = lane & 15;
    int node = w * 2 + half;
    if (node >= n) return;
    int beg = g_off[node], end = g_off[node + 1];
    int col = l16 * 4;
    float4 acc = make_float4(0.f, 0.f, 0.f, 0.f);
    int e = beg;
    for (; e + 4 <= end; e += 4) {
        int s0 = g_esrc[e], s1 = g_esrc[e + 1], s2 = g_esrc[e + 2], s3 = g_esrc[e + 3];
        float4 v0 = *reinterpret_cast<const float4*>(rows + (size_t)s0 * OUT_F + col);
        float4 v1 = *reinterpret_cast<const float4*>(rows + (size_t)s1 * OUT_F + col);
        float4 v2 = *reinterpret_cast<const float4*>(rows + (size_t)s2 * OUT_F + col);
        float4 v3 = *reinterpret_cast<const float4*>(rows + (size_t)s3 * OUT_F + col);
        acc = f4add(acc, f4add(f4add(v0, v1), f4add(v2, v3)));
    }
    for (; e < end; e++) {
        int s = g_esrc[e];
        float4 v = *reinterpret_cast<const float4*>(rows + (size_t)s * OUT_F + col);
        acc = f4add(acc, v);
    }
    float inv = (end > beg) ? 1.0f / (float)(end - beg) : 0.0f;
    float4* po = reinterpret_cast<float4*>(out + (size_t)node * OUT_F + col);
    float4 o = *po;
    *po = make_float4(o.x + acc.x * inv, o.y + acc.y * inv,
                      o.z + acc.z * inv, o.w + acc.w * inv);
}

// ---------------- K5: h1 = relu(h@W1s + hn1@W1n + b1) ------------------------
__global__ void k_node1(const float* __restrict__ W1s,
                        const float* __restrict__ W1n,
                        const float* __restrict__ b1, int n) {
    __shared__ float hs[16][CAT_F];
    __shared__ float hn[16][CAT_F];
    int tid = threadIdx.x;
    int node0 = blockIdx.x * 16;
    for (int i = tid; i < 16 * CAT_F; i += 128) {
        int r = i / CAT_F, k = i - r * CAT_F;
        int nd = node0 + r;
        if (nd < n) {
            hs[r][k] = g_h  [nd * CAT_F + k];
            hn[r][k] = g_hn1[nd * CAT_F + k];
        }
    }
    __syncthreads();
    int j = tid;
    float acc[16];
    float bj = b1[j];
    #pragma unroll
    for (int i = 0; i < 16; i++) acc[i] = bj;
    for (int k = 0; k < CAT_F; k++) {
        float ws = W1s[k * HID_F + j];
        float wn = W1n[k * HID_F + j];
        #pragma unroll
        for (int i = 0; i < 16; i++)
            acc[i] = fmaf(hs[i][k], ws, fmaf(hn[i][k], wn, acc[i]));
    }
    #pragma unroll
    for (int i = 0; i < 16; i++) {
        int nd = node0 + i;
        if (nd < n) g_h1[nd * HID_F + j] = fmaxf(acc[i], 0.0f);
    }
}

// ---------------- K6: out = h1@W2s + b2 ; z2 = h1@W2n ------------------------
__global__ void k_node2a(const float* __restrict__ W2s,
                         const float* __restrict__ W2n,
                         const float* __restrict__ b2,
                         float* __restrict__ out, int n) {
    __shared__ float hs[16][HID_F];
    int tid = threadIdx.x;
    int node0 = blockIdx.x * 16;
    for (int i = tid; i < 16 * HID_F; i += 64) {
        int r = i >> 7, k = i & 127;
        int nd = node0 + r;
        if (nd < n) hs[r][k] = g_h1[nd * HID_F + k];
    }
    __syncthreads();
    int j = tid;
    float accs[16], accz[16];
    float bj = b2[j];
    #pragma unroll
    for (int i = 0; i < 16; i++) { accs[i] = bj; accz[i] = 0.0f; }
    for (int k = 0; k < HID_F; k++) {
        float ws = W2s[k * OUT_F + j];
        float wn = W2n[k * OUT_F + j];
        #pragma unroll
        for (int i = 0; i < 16; i++) {
            accs[i] = fmaf(hs[i][k], ws, accs[i]);
            accz[i] = fmaf(hs[i][k], wn, accz[i]);
        }
    }
    #pragma unroll
    for (int i = 0; i < 16; i++) {
        int nd = node0 + i;
        if (nd < n) {
            out [nd * OUT_F + j] = accs[i];
            g_z2[nd * OUT_F + j] = accz[i];
        }
    }
}

// ---------------- launch -----------------------------------------------------
extern "C" void kernel_launch(void* const* d_in, const int* in_sizes, int n_in,
                              void* d_out, int out_size) {
    const float* nfeat = (const float*)d_in[0];
    const float* efeat = (const float*)d_in[1];
    const int*   src   = (const int*)  d_in[2];
    const int*   dst   = (const int*)  d_in[3];
    const float* We    = (const float*)d_in[4];
    const float* be    = (const float*)d_in[5];
    const float* W1s   = (const float*)d_in[6];
    const float* W1n   = (const float*)d_in[7];
    const float* b1    = (const float*)d_in[8];
    const float* W2s   = (const float*)d_in[9];
    const float* W2n   = (const float*)d_in[10];
    const float* b2    = (const float*)d_in[11];
    float* out = (float*)d_out;

    int n = in_sizes[0] / IN_F;
    int E = in_sizes[2];

    void *p_degi, *p_acc0, *p_h, *p_hn1, *p_h1, *p_z2;
    cudaGetSymbolAddress(&p_degi, g_degi);
    cudaGetSymbolAddress(&p_acc0, g_acc0);
    cudaGetSymbolAddress(&p_h,    g_h);
    cudaGetSymbolAddress(&p_hn1,  g_hn1);
    cudaGetSymbolAddress(&p_h1,   g_h1);
    cudaGetSymbolAddress(&p_z2,   g_z2);

    cudaMemsetAsync(p_degi, 0, (size_t)n * sizeof(int), 0);
    cudaMemsetAsync(p_acc0, 0, (size_t)n * IN_F * sizeof(float), 0);

    // --- CSR build (by dst) ---
    int nb = (n + 1023) / 1024;
    k_degi <<<(E + 255) / 256, 256>>>(dst, E);
    k_scan1<<<nb, 1024>>>(n);
    k_scan2<<<1, 128>>>(nb);
    k_scan3<<<(n + 255) / 256, 256>>>(n, E);
    k_fill <<<(E + 255) / 256, 256>>>(src, dst, E);

    // --- layer 0: edge encoder + u_mul_e + mean (scatter path) ---
    k_msg1<<<2048, 256>>>(nfeat, efeat, src, dst, We, be, E);
    k_finh<<<(n * IN_F + 255) / 256, 256>>>(nfeat, n);

    // --- layer 1: gather-mean + GEMM ---
    k_gather96<<<(n + 7) / 8, 256>>>((const float*)p_h, (float*)p_hn1, n);
    k_node1<<<(n + 15) / 16, 128>>>(W1s, W1n, b1, n);

    // --- layer 2: GEMMs then width-64 gather-mean-add ---
    k_node2a<<<(n + 15) / 16, 64>>>(W2s, W2n, b2, out, n);
    k_gather64_add<<<(n + 15) / 16, 256>>>((const float*)p_z2, out, n);
}